// round 6
// baseline (speedup 1.0000x reference)
#include <cuda_runtime.h>
#include <cuda_bf16.h>
#include <cstdint>
#include <math.h>

// Problem constants
#define Bq   8
#define Sq   1024
#define Dq   512
#define Hq   8
#define DHq  64
#define BSr  (Bq*Sq)        // 8192 rows
#define BSD  (Bq*Sq*Dq)     // 4194304 elements

// ---------------- device scratch (no allocations allowed) ----------------
__device__ float g_E [BSD];
__device__ float g_DI[BSD];
__device__ float g_S [BSD];
__device__ float g_I [BSD];
__device__ float g_EO[BSD];
__device__ __nv_bfloat16 g_Ahi[BSD], g_Alo[BSD];
__device__ __nv_bfloat16 g_Qhi[BSD], g_Qlo[BSD];
__device__ __nv_bfloat16 g_Khi[BSD], g_Klo[BSD];
__device__ __nv_bfloat16 g_Vhi[BSD], g_Vlo[BSD];
__device__ __nv_bfloat16 g_EOhi[BSD], g_EOlo[BSD];
__device__ __nv_bfloat16 g_Wthi[8 * Dq * Dq];   // transposed weights [n][k], hi
__device__ __nv_bfloat16 g_Wtlo[8 * Dq * Dq];   // lo

// ---------------- helpers (non-'a' ISA only) ----------------
__device__ __forceinline__ uint32_t smem_u32(const void* p) {
    uint32_t a;
    asm("{ .reg .u64 t; cvta.to.shared.u64 t, %1; cvt.u32.u64 %0, t; }" : "=r"(a) : "l"(p));
    return a;
}
__device__ __forceinline__ void ldsm_x4(uint32_t* r, uint32_t addr) {
    asm volatile("ldmatrix.sync.aligned.m8n8.x4.shared.b16 {%0,%1,%2,%3}, [%4];"
        : "=r"(r[0]), "=r"(r[1]), "=r"(r[2]), "=r"(r[3]) : "r"(addr));
}
__device__ __forceinline__ void ldsm_x2(uint32_t* r, uint32_t addr) {
    asm volatile("ldmatrix.sync.aligned.m8n8.x2.shared.b16 {%0,%1}, [%2];"
        : "=r"(r[0]), "=r"(r[1]) : "r"(addr));
}
__device__ __forceinline__ void ldsm_x2t(uint32_t* r, uint32_t addr) {
    asm volatile("ldmatrix.sync.aligned.m8n8.x2.trans.shared.b16 {%0,%1}, [%2];"
        : "=r"(r[0]), "=r"(r[1]) : "r"(addr));
}
__device__ __forceinline__ void mma16816(float* c, const uint32_t* a, const uint32_t* b) {
    asm volatile("mma.sync.aligned.m16n8k16.row.col.f32.bf16.bf16.f32 "
        "{%0,%1,%2,%3}, {%4,%5,%6,%7}, {%8,%9}, {%0,%1,%2,%3};"
        : "+f"(c[0]), "+f"(c[1]), "+f"(c[2]), "+f"(c[3])
        : "r"(a[0]), "r"(a[1]), "r"(a[2]), "r"(a[3]), "r"(b[0]), "r"(b[1]));
}
__device__ __forceinline__ void splitpk(float a, float b, uint32_t& hi, uint32_t& lo) {
    __nv_bfloat162 h = __floats2bfloat162_rn(a, b);
    float ra = a - __bfloat162float(h.x);
    float rb = b - __bfloat162float(h.y);
    __nv_bfloat162 l = __floats2bfloat162_rn(ra, rb);
    hi = *(uint32_t*)&h; lo = *(uint32_t*)&l;
}
#define CPA16(sa, gp) asm volatile("cp.async.cg.shared.global [%0], [%1], 16;" :: "r"(sa), "l"(gp))
#define CP_COMMIT()   asm volatile("cp.async.commit_group;")
#define CP_WAIT1()    asm volatile("cp.async.wait_group 1;" ::: "memory")

// ---------------- fused weight convert + transpose (all 8) ----------------
__global__ void __launch_bounds__(256) cvt_wt_all_kernel(
    const float* __restrict__ W0, const float* __restrict__ W1,
    const float* __restrict__ W2, const float* __restrict__ W3,
    const float* __restrict__ W4, const float* __restrict__ W5,
    const float* __restrict__ W6, const float* __restrict__ W7,
    __nv_bfloat16* __restrict__ hi, __nv_bfloat16* __restrict__ lo) {
    int w = blockIdx.y;
    const float* W = (w == 0) ? W0 : (w == 1) ? W1 : (w == 2) ? W2 : (w == 3) ? W3 :
                     (w == 4) ? W4 : (w == 5) ? W5 : (w == 6) ? W6 : W7;
    int idx = blockIdx.x * 256 + threadIdx.x;   // idx = n*512 + k
    int n = idx >> 9, k = idx & 511;
    float v = W[k * Dq + n];
    __nv_bfloat16 h = __float2bfloat16(v);
    size_t o = (size_t)w * Dq * Dq + idx;
    hi[o] = h;
    lo[o] = __float2bfloat16(v - __bfloat162float(h));
}

// ---------------- positional-embedding add (fp32 + split bf16 out) ----------------
__global__ void __launch_bounds__(256) add_pos_kernel(const float* __restrict__ x,
                                                      float* __restrict__ out,
                                                      __nv_bfloat16* __restrict__ ohi,
                                                      __nv_bfloat16* __restrict__ olo) {
    int idx = blockIdx.x * 256 + threadIdx.x;
    int d = idx & (Dq - 1);
    int s = (idx >> 9) & (Sq - 1);
    float freq  = expf((float)d * -0.0359778920794f);
    float angle = (float)s * freq;
    float pe = (d & 1) ? cosf(angle) : sinf(angle);
    float r = x[idx] + pe;
    out[idx] = r;
    __nv_bfloat16 h = __float2bfloat16(r);
    ohi[idx] = h;
    olo[idx] = __float2bfloat16(r - __bfloat162float(h));
}

// ---------------- fused LayerNorm + residual ----------------
__global__ void __launch_bounds__(256) ln_add_kernel(const float* __restrict__ x,
                                                     const float* __restrict__ gamma,
                                                     const float* __restrict__ beta,
                                                     const float* __restrict__ basep,
                                                     float scale,
                                                     float* __restrict__ out,
                                                     __nv_bfloat16* __restrict__ ohi,
                                                     __nv_bfloat16* __restrict__ olo) {
    __shared__ float red[256];
    int t = threadIdx.x;
    size_t off = (size_t)blockIdx.x * Dq;

    float v0 = x[off + t];
    float v1 = x[off + t + 256];

    red[t] = v0 + v1;
    __syncthreads();
    #pragma unroll
    for (int s2 = 128; s2 > 0; s2 >>= 1) {
        if (t < s2) red[t] += red[t + s2];
        __syncthreads();
    }
    float mu = red[0] * (1.0f / 512.0f);
    __syncthreads();

    float d0 = v0 - mu, d1 = v1 - mu;
    red[t] = d0 * d0 + d1 * d1;
    __syncthreads();
    #pragma unroll
    for (int s2 = 128; s2 > 0; s2 >>= 1) {
        if (t < s2) red[t] += red[t + s2];
        __syncthreads();
    }
    float var = red[0] * (1.0f / 512.0f);
    float rs  = rsqrtf(var + 1e-3f);

    float r0 = basep[off + t]       + scale * (d0 * rs * gamma[t]       + beta[t]);
    float r1 = basep[off + t + 256] + scale * (d1 * rs * gamma[t + 256] + beta[t + 256]);
    out[off + t]       = r0;
    out[off + t + 256] = r1;
    if (ohi) {
        __nv_bfloat16 h0 = __float2bfloat16(r0), h1 = __float2bfloat16(r1);
        ohi[off + t]       = h0;
        ohi[off + t + 256] = h1;
        olo[off + t]       = __float2bfloat16(r0 - __bfloat162float(h0));
        olo[off + t + 256] = __float2bfloat16(r1 - __bfloat162float(h1));
    }
}

// ---------------- mma.sync split-bf16 GEMM, cp.async double-buffered ----------------
#define APAD 72
#define SA_HI 0
#define SA_LO 18432
#define SB_HI 36864
#define SB_LO 46080
#define GBUF  55296
#define GEMM_SMEM (2 * GBUF)   // 110592

__global__ void __launch_bounds__(256) gemm_mma_kernel(const __nv_bfloat16* __restrict__ Ahi,
                                                       const __nv_bfloat16* __restrict__ Alo,
                                                       const __nv_bfloat16* __restrict__ Bhi,
                                                       const __nv_bfloat16* __restrict__ Blo,
                                                       const float* __restrict__ addend,
                                                       float* __restrict__ C,
                                                       __nv_bfloat16* __restrict__ Chi,
                                                       __nv_bfloat16* __restrict__ Clo) {
    extern __shared__ char smem[];
    uint32_t sb = smem_u32(smem);

    int tid = threadIdx.x;
    int wid = tid >> 5, lane = tid & 31;
    int wm = (wid & 3) * 32;
    int wn = (wid >> 2) * 32;
    int m0 = blockIdx.y * 128;
    int n0 = blockIdx.x * 64;

    // per-thread load coordinates
    int rA = tid >> 1, cA = (tid & 1) * 32;            // A: 128 rows, 2 thr/row, 32 cols each (4 u4)
    int rB = tid >> 2, cB = (tid & 3) * 16;            // B: 64 rows, 4 thr/row, 16 cols each (2 u4)

    // prefetch chunk kc into buffer buf
    auto prefetch = [&](int kc, uint32_t bofs) {
        int kofs = kc * 64;
        const __nv_bfloat16* pAh = &Ahi[(size_t)(m0 + rA) * Dq + kofs + cA];
        const __nv_bfloat16* pAl = &Alo[(size_t)(m0 + rA) * Dq + kofs + cA];
        uint32_t sAo = sb + bofs + (uint32_t)((rA * APAD + cA) * 2);
        #pragma unroll
        for (int q = 0; q < 4; q++) {
            CPA16(sAo + SA_HI + q * 16, pAh + q * 8);
            CPA16(sAo + SA_LO + q * 16, pAl + q * 8);
        }
        const __nv_bfloat16* pBh = &Bhi[(size_t)(n0 + rB) * Dq + kofs + cB];
        const __nv_bfloat16* pBl = &Blo[(size_t)(n0 + rB) * Dq + kofs + cB];
        uint32_t sBo = sb + bofs + (uint32_t)((rB * APAD + cB) * 2);
        #pragma unroll
        for (int q = 0; q < 2; q++) {
            CPA16(sBo + SB_HI + q * 16, pBh + q * 8);
            CPA16(sBo + SB_LO + q * 16, pBl + q * 8);
        }
    };

    float acc[2][4][4];
    #pragma unroll
    for (int i = 0; i < 2; i++)
        #pragma unroll
        for (int j = 0; j < 4; j++)
            #pragma unroll
            for (int q = 0; q < 4; q++) acc[i][j][q] = 0.0f;

    int la = lane & 15;
    int lacol = (lane >> 4) << 3;
    int lb = lane & 7;
    int lbcol = ((lane >> 3) & 1) << 3;

    prefetch(0, 0);
    CP_COMMIT();

    for (int kc = 0; kc < 8; kc++) {
        uint32_t cur = (kc & 1) ? GBUF : 0;
        if (kc < 7) prefetch(kc + 1, (kc & 1) ? 0 : GBUF);
        CP_COMMIT();
        CP_WAIT1();
        __syncthreads();

        #pragma unroll
        for (int ks = 0; ks < 4; ks++) {
            int kk = ks * 16;
            uint32_t ah[2][4], al[2][4];
            #pragma unroll
            for (int ma = 0; ma < 2; ma++) {
                int row = wm + ma * 16 + la;
                uint32_t off = cur + (uint32_t)((row * APAD + kk + lacol) * 2);
                ldsm_x4(ah[ma], sb + SA_HI + off);
                ldsm_x4(al[ma], sb + SA_LO + off);
            }
            uint32_t bh[4][2], bl[4][2];
            #pragma unroll
            for (int na = 0; na < 4; na++) {
                int rown = wn + na * 8 + lb;
                uint32_t off = cur + (uint32_t)((rown * APAD + kk + lbcol) * 2);
                ldsm_x2(bh[na], sb + SB_HI + off);
                ldsm_x2(bl[na], sb + SB_LO + off);
            }
            #pragma unroll
            for (int ma = 0; ma < 2; ma++)
                #pragma unroll
                for (int na = 0; na < 4; na++) {
                    mma16816(acc[ma][na], ah[ma], bh[na]);
                    mma16816(acc[ma][na], al[ma], bh[na]);
                    mma16816(acc[ma][na], ah[ma], bl[na]);
                }
        }
        __syncthreads();
    }

    int g = lane >> 2, tq = lane & 3;
    #pragma unroll
    for (int ma = 0; ma < 2; ma++) {
        int row = m0 + wm + ma * 16 + g;
        #pragma unroll
        for (int na = 0; na < 4; na++) {
            int col = n0 + wn + na * 8 + tq * 2;
            size_t o0 = (size_t)row * Dq + col;
            size_t o1 = o0 + 8 * Dq;
            float2 r0 = make_float2(acc[ma][na][0], acc[ma][na][1]);
            float2 r1 = make_float2(acc[ma][na][2], acc[ma][na][3]);
            if (addend) {
                float2 a0 = *(const float2*)&addend[o0];
                float2 a1 = *(const float2*)&addend[o1];
                r0.x += a0.x; r0.y += a0.y;
                r1.x += a1.x; r1.y += a1.y;
            }
            if (C) {
                *(float2*)&C[o0] = r0;
                *(float2*)&C[o1] = r1;
            }
            if (Chi) {
                uint32_t h, l;
                splitpk(r0.x, r0.y, h, l);
                *(uint32_t*)&Chi[o0] = h; *(uint32_t*)&Clo[o0] = l;
                splitpk(r1.x, r1.y, h, l);
                *(uint32_t*)&Chi[o1] = h; *(uint32_t*)&Clo[o1] = l;
            }
        }
    }
}

// ---------------- mma.sync flash attention, 128q tiles + cp.async ----------------
#define FP 72
#define FQHI 0
#define FQLO 18432
#define FKV  36864          // start of double buffers
#define KVH  0
#define KVL  9216
#define VVH  18432
#define VVL  27648
#define KVBUF 36864
#define FLASH_SMEM (FKV + 2 * KVBUF)   // 110592

__global__ void __launch_bounds__(256) flash_mma_kernel(
    const __nv_bfloat16* __restrict__ Qh, const __nv_bfloat16* __restrict__ Ql,
    const __nv_bfloat16* __restrict__ Kh, const __nv_bfloat16* __restrict__ Kl,
    const __nv_bfloat16* __restrict__ Vh, const __nv_bfloat16* __restrict__ Vl,
    float* __restrict__ O,
    __nv_bfloat16* __restrict__ Ohi, __nv_bfloat16* __restrict__ Olo) {
    extern __shared__ char smem[];
    uint32_t sb = smem_u32(smem);

    int tid = threadIdx.x, wid = tid >> 5, lane = tid & 31;
    int wm = wid * 16;                                   // 8 warps x 16 q-rows = 128
    int g = lane >> 2, tq = lane & 3;
    int qb = blockIdx.x, h = blockIdx.y, b = blockIdx.z;
    size_t baseQ  = ((size_t)b * Sq + (size_t)qb * 128) * Dq + h * DHq;
    size_t baseKV = (size_t)b * Sq * Dq + h * DHq;

    // Q load coordinates: 128 rows, 2 thr/row, 32 cols each
    int rQ = tid >> 1, cQ = (tid & 1) * 32;
    // KV load coordinates: 64 rows, 4 thr/row, 16 cols each
    int rK = tid >> 2, cK = (tid & 3) * 16;

    auto kvload = [&](int kb, uint32_t bofs) {
        size_t go = baseKV + (size_t)(kb * 64 + rK) * Dq + cK;
        uint32_t so = sb + FKV + bofs + (uint32_t)((rK * FP + cK) * 2);
        #pragma unroll
        for (int q = 0; q < 2; q++) {
            CPA16(so + KVH + q * 16, &Kh[go + q * 8]);
            CPA16(so + KVL + q * 16, &Kl[go + q * 8]);
            CPA16(so + VVH + q * 16, &Vh[go + q * 8]);
            CPA16(so + VVL + q * 16, &Vl[go + q * 8]);
        }
    };

    // group 0: Q + KV tile 0
    {
        size_t go = baseQ + (size_t)rQ * Dq + cQ;
        uint32_t so = sb + (uint32_t)((rQ * FP + cQ) * 2);
        #pragma unroll
        for (int q = 0; q < 4; q++) {
            CPA16(so + FQHI + q * 16, &Qh[go + q * 8]);
            CPA16(so + FQLO + q * 16, &Ql[go + q * 8]);
        }
        kvload(0, 0);
        CP_COMMIT();
    }

    float oacc[8][4];
    #pragma unroll
    for (int j = 0; j < 8; j++)
        #pragma unroll
        for (int q = 0; q < 4; q++) oacc[j][q] = 0.0f;
    float mr0 = -1e30f, mr1 = -1e30f, lr0 = 0.0f, lr1 = 0.0f;

    uint32_t aQ = (uint32_t)(((wm + (lane & 15)) * FP + ((lane >> 4) << 3)) * 2);
    uint32_t bK = (uint32_t)(((lane & 7) * FP + (((lane >> 3) & 1) << 3)) * 2);
    uint32_t bV = (uint32_t)(((lane & 15) * FP) * 2);

    for (int kb = 0; kb < 16; kb++) {
        uint32_t cur = FKV + ((kb & 1) ? KVBUF : 0);
        if (kb < 15) kvload(kb + 1, (kb & 1) ? 0 : KVBUF);
        CP_COMMIT();
        CP_WAIT1();
        __syncthreads();

        // S = Q @ K^T (3-pass split)
        float sacc[8][4];
        #pragma unroll
        for (int j = 0; j < 8; j++)
            #pragma unroll
            for (int q = 0; q < 4; q++) sacc[j][q] = 0.0f;

        #pragma unroll
        for (int ks = 0; ks < 4; ks++) {
            uint32_t ah[4], al[4];
            ldsm_x4(ah, sb + FQHI + aQ + ks * 32);
            ldsm_x4(al, sb + FQLO + aQ + ks * 32);
            #pragma unroll
            for (int na = 0; na < 8; na++) {
                uint32_t bh[2], bl[2];
                uint32_t off = cur + bK + (uint32_t)(na * 8 * FP * 2) + ks * 32;
                ldsm_x2(bh, sb + KVH + off);
                ldsm_x2(bl, sb + KVL + off);
                mma16816(sacc[na], ah, bh);
                mma16816(sacc[na], al, bh);
                mma16816(sacc[na], ah, bl);
            }
        }

        // Register softmax
        float rmax0 = -1e30f, rmax1 = -1e30f;
        #pragma unroll
        for (int j = 0; j < 8; j++) {
            sacc[j][0] *= 0.125f; sacc[j][1] *= 0.125f;
            sacc[j][2] *= 0.125f; sacc[j][3] *= 0.125f;
            rmax0 = fmaxf(rmax0, fmaxf(sacc[j][0], sacc[j][1]));
            rmax1 = fmaxf(rmax1, fmaxf(sacc[j][2], sacc[j][3]));
        }
        rmax0 = fmaxf(rmax0, __shfl_xor_sync(0xffffffffu, rmax0, 1));
        rmax0 = fmaxf(rmax0, __shfl_xor_sync(0xffffffffu, rmax0, 2));
        rmax1 = fmaxf(rmax1, __shfl_xor_sync(0xffffffffu, rmax1, 1));
        rmax1 = fmaxf(rmax1, __shfl_xor_sync(0xffffffffu, rmax1, 2));
        float mn0 = fmaxf(mr0, rmax0), mn1 = fmaxf(mr1, rmax1);
        float al0 = __expf(mr0 - mn0), al1 = __expf(mr1 - mn1);
        float sum0 = 0.0f, sum1 = 0.0f;
        #pragma unroll
        for (int j = 0; j < 8; j++) {
            sacc[j][0] = __expf(sacc[j][0] - mn0);
            sacc[j][1] = __expf(sacc[j][1] - mn0);
            sacc[j][2] = __expf(sacc[j][2] - mn1);
            sacc[j][3] = __expf(sacc[j][3] - mn1);
            sum0 += sacc[j][0] + sacc[j][1];
            sum1 += sacc[j][2] + sacc[j][3];
        }
        sum0 += __shfl_xor_sync(0xffffffffu, sum0, 1);
        sum0 += __shfl_xor_sync(0xffffffffu, sum0, 2);
        sum1 += __shfl_xor_sync(0xffffffffu, sum1, 1);
        sum1 += __shfl_xor_sync(0xffffffffu, sum1, 2);
        lr0 = lr0 * al0 + sum0; mr0 = mn0;
        lr1 = lr1 * al1 + sum1; mr1 = mn1;

        #pragma unroll
        for (int j = 0; j < 8; j++) {
            oacc[j][0] *= al0; oacc[j][1] *= al0;
            oacc[j][2] *= al1; oacc[j][3] *= al1;
        }

        // Re-pack P into A fragments, split hi/lo
        uint32_t ph[4][4], pl[4][4];
        #pragma unroll
        for (int k2 = 0; k2 < 4; k2++) {
            splitpk(sacc[2*k2][0],   sacc[2*k2][1],   ph[k2][0], pl[k2][0]);
            splitpk(sacc[2*k2][2],   sacc[2*k2][3],   ph[k2][1], pl[k2][1]);
            splitpk(sacc[2*k2+1][0], sacc[2*k2+1][1], ph[k2][2], pl[k2][2]);
            splitpk(sacc[2*k2+1][2], sacc[2*k2+1][3], ph[k2][3], pl[k2][3]);
        }

        // O += P @ V (3-pass split; V via ldmatrix.trans)
        #pragma unroll
        for (int k2 = 0; k2 < 4; k2++) {
            #pragma unroll
            for (int na = 0; na < 8; na++) {
                uint32_t bvh[2], bvl[2];
                uint32_t off = cur + bV + (uint32_t)((k2 * 16 * FP + na * 8) * 2);
                ldsm_x2t(bvh, sb + VVH + off);
                ldsm_x2t(bvl, sb + VVL + off);
                mma16816(oacc[na], ph[k2], bvh);
                mma16816(oacc[na], pl[k2], bvh);
                mma16816(oacc[na], ph[k2], bvl);
            }
        }
        __syncthreads();
    }

    // Final normalize + store
    float il0 = 1.0f / lr0, il1 = 1.0f / lr1;
    int row0 = wm + g, row1 = wm + g + 8;
    #pragma unroll
    for (int na = 0; na < 8; na++) {
        int col = na * 8 + tq * 2;
        float v00 = oacc[na][0] * il0, v01 = oacc[na][1] * il0;
        float v10 = oacc[na][2] * il1, v11 = oacc[na][3] * il1;
        size_t o0 = baseQ + (size_t)row0 * Dq + col;
        size_t o1 = baseQ + (size_t)row1 * Dq + col;
        if (O) {
            *(float2*)&O[o0] = make_float2(v00, v01);
            *(float2*)&O[o1] = make_float2(v10, v11);
        }
        if (Ohi) {
            uint32_t hh, ll;
            splitpk(v00, v01, hh, ll);
            *(uint32_t*)&Ohi[o0] = hh; *(uint32_t*)&Olo[o0] = ll;
            splitpk(v10, v11, hh, ll);
            *(uint32_t*)&Ohi[o1] = hh; *(uint32_t*)&Olo[o1] = ll;
        }
    }
}

// ---------------- launcher ----------------
extern "C" void kernel_launch(void* const* d_in, const int* in_sizes, int n_in,
                              void* d_out, int out_size) {
    const float* in0   = (const float*)d_in[0];
    const float* in1   = (const float*)d_in[1];
    const float* ge = (const float*)d_in[6];
    const float* be = (const float*)d_in[7];
    const float* gd = (const float*)d_in[12];
    const float* bd = (const float*)d_in[13];
    float* out = (float*)d_out;

    float *E, *DI, *Sb, *I, *EO;
    __nv_bfloat16 *Ahi, *Alo, *Qhi, *Qlo, *Khi, *Klo, *Vhi, *Vlo, *EOhi, *EOlo, *Whi, *Wlo;
    cudaGetSymbolAddress((void**)&E,    g_E);
    cudaGetSymbolAddress((void**)&DI,   g_DI);
    cudaGetSymbolAddress((void**)&Sb,   g_S);
    cudaGetSymbolAddress((void**)&I,    g_I);
    cudaGetSymbolAddress((void**)&EO,   g_EO);
    cudaGetSymbolAddress((void**)&Ahi,  g_Ahi);
    cudaGetSymbolAddress((void**)&Alo,  g_Alo);
    cudaGetSymbolAddress((void**)&Qhi,  g_Qhi);
    cudaGetSymbolAddress((void**)&Qlo,  g_Qlo);
    cudaGetSymbolAddress((void**)&Khi,  g_Khi);
    cudaGetSymbolAddress((void**)&Klo,  g_Klo);
    cudaGetSymbolAddress((void**)&Vhi,  g_Vhi);
    cudaGetSymbolAddress((void**)&Vlo,  g_Vlo);
    cudaGetSymbolAddress((void**)&EOhi, g_EOhi);
    cudaGetSymbolAddress((void**)&EOlo, g_EOlo);
    cudaGetSymbolAddress((void**)&Whi,  g_Wthi);
    cudaGetSymbolAddress((void**)&Wlo,  g_Wtlo);

    cudaFuncSetAttribute(gemm_mma_kernel,  cudaFuncAttributeMaxDynamicSharedMemorySize, GEMM_SMEM);
    cudaFuncSetAttribute(flash_mma_kernel, cudaFuncAttributeMaxDynamicSharedMemorySize, FLASH_SMEM);

    dim3 ggrid(Dq / 64, BSr / 128);       // (8, 64)
    dim3 fgrid(Sq / 128, Hq, Bq);         // (8, 8, 8)
    const int WSZ = Dq * Dq;

    dim3 wgrid(WSZ / 256, 8);
    cvt_wt_all_kernel<<<wgrid, 256>>>(
        (const float*)d_in[2], (const float*)d_in[3], (const float*)d_in[4],
        (const float*)d_in[5], (const float*)d_in[8], (const float*)d_in[9],
        (const float*)d_in[10], (const float*)d_in[11], Whi, Wlo);

    // ---- Encoder ----
    add_pos_kernel<<<BSD / 256, 256>>>(in0, E, Ahi, Alo);
    gemm_mma_kernel<<<ggrid, 256, GEMM_SMEM>>>(Ahi, Alo, Whi + 0 * WSZ, Wlo + 0 * WSZ, nullptr, nullptr, Qhi, Qlo);
    gemm_mma_kernel<<<ggrid, 256, GEMM_SMEM>>>(Ahi, Alo, Whi + 1 * WSZ, Wlo + 1 * WSZ, nullptr, nullptr, Khi, Klo);
    gemm_mma_kernel<<<ggrid, 256, GEMM_SMEM>>>(Ahi, Alo, Whi + 2 * WSZ, Wlo + 2 * WSZ, nullptr, nullptr, Vhi, Vlo);
    flash_mma_kernel<<<fgrid, 256, FLASH_SMEM>>>(Qhi, Qlo, Khi, Klo, Vhi, Vlo, Sb, nullptr, nullptr);
    ln_add_kernel<<<BSr, 256>>>(Sb, ge, be, E, 1.0f, I, Ahi, Alo);
    gemm_mma_kernel<<<ggrid, 256, GEMM_SMEM>>>(Ahi, Alo, Whi + 3 * WSZ, Wlo + 3 * WSZ, E, EO, EOhi, EOlo);

    // ---- Decoder ----
    add_pos_kernel<<<BSD / 256, 256>>>(in1, DI, Ahi, Alo);
    gemm_mma_kernel<<<ggrid, 256, GEMM_SMEM>>>(Ahi, Alo, Whi + 4 * WSZ, Wlo + 4 * WSZ, nullptr, nullptr, Qhi, Qlo);
    gemm_mma_kernel<<<ggrid, 256, GEMM_SMEM>>>(Ahi, Alo, Whi + 5 * WSZ, Wlo + 5 * WSZ, nullptr, nullptr, Khi, Klo);
    gemm_mma_kernel<<<ggrid, 256, GEMM_SMEM>>>(Ahi, Alo, Whi + 6 * WSZ, Wlo + 6 * WSZ, nullptr, nullptr, Vhi, Vlo);
    flash_mma_kernel<<<fgrid, 256, FLASH_SMEM>>>(Qhi, Qlo, Khi, Klo, Vhi, Vlo, Sb, nullptr, nullptr);
    ln_add_kernel<<<BSr, 256>>>(Sb, gd, bd, DI, 2.0f, I, nullptr, nullptr);
    flash_mma_kernel<<<fgrid, 256, FLASH_SMEM>>>(EOhi, EOlo, EOhi, EOlo, EOhi, EOlo,
                                                 nullptr, Ahi, Alo);   // eda -> bf16 only
    gemm_mma_kernel<<<ggrid, 256, GEMM_SMEM>>>(Ahi, Alo, Whi + 7 * WSZ, Wlo + 7 * WSZ, I, out, nullptr, nullptr);
}

// round 7
// speedup vs baseline: 1.1029x; 1.1029x over previous
#include <cuda_runtime.h>
#include <cuda_bf16.h>
#include <cstdint>
#include <math.h>

// Problem constants
#define Bq   8
#define Sq   1024
#define Dq   512
#define Hq   8
#define DHq  64
#define BSr  (Bq*Sq)        // 8192 rows
#define BSD  (Bq*Sq*Dq)     // 4194304 elements

// ---------------- device scratch (no allocations allowed) ----------------
__device__ float g_E [BSD];
__device__ float g_DI[BSD];
__device__ float g_S [BSD];
__device__ float g_I [BSD];
__device__ float g_EO[BSD];
__device__ __nv_bfloat16 g_Ahi[BSD], g_Alo[BSD];
__device__ __nv_bfloat16 g_Qhi[BSD], g_Qlo[BSD];
__device__ __nv_bfloat16 g_Khi[BSD], g_Klo[BSD];
__device__ __nv_bfloat16 g_Vhi[BSD], g_Vlo[BSD];
__device__ __nv_bfloat16 g_EOhi[BSD], g_EOlo[BSD];
__device__ __nv_bfloat16 g_Wthi[8 * Dq * Dq];   // transposed weights [n][k], hi
__device__ __nv_bfloat16 g_Wtlo[8 * Dq * Dq];   // lo

// ---------------- helpers (non-'a' ISA only) ----------------
__device__ __forceinline__ uint32_t smem_u32(const void* p) {
    uint32_t a;
    asm("{ .reg .u64 t; cvta.to.shared.u64 t, %1; cvt.u32.u64 %0, t; }" : "=r"(a) : "l"(p));
    return a;
}
__device__ __forceinline__ void ldsm_x4(uint32_t* r, uint32_t addr) {
    asm volatile("ldmatrix.sync.aligned.m8n8.x4.shared.b16 {%0,%1,%2,%3}, [%4];"
        : "=r"(r[0]), "=r"(r[1]), "=r"(r[2]), "=r"(r[3]) : "r"(addr));
}
__device__ __forceinline__ void ldsm_x2(uint32_t* r, uint32_t addr) {
    asm volatile("ldmatrix.sync.aligned.m8n8.x2.shared.b16 {%0,%1}, [%2];"
        : "=r"(r[0]), "=r"(r[1]) : "r"(addr));
}
__device__ __forceinline__ void ldsm_x2t(uint32_t* r, uint32_t addr) {
    asm volatile("ldmatrix.sync.aligned.m8n8.x2.trans.shared.b16 {%0,%1}, [%2];"
        : "=r"(r[0]), "=r"(r[1]) : "r"(addr));
}
__device__ __forceinline__ void mma16816(float* c, const uint32_t* a, const uint32_t* b) {
    asm volatile("mma.sync.aligned.m16n8k16.row.col.f32.bf16.bf16.f32 "
        "{%0,%1,%2,%3}, {%4,%5,%6,%7}, {%8,%9}, {%0,%1,%2,%3};"
        : "+f"(c[0]), "+f"(c[1]), "+f"(c[2]), "+f"(c[3])
        : "r"(a[0]), "r"(a[1]), "r"(a[2]), "r"(a[3]), "r"(b[0]), "r"(b[1]));
}
__device__ __forceinline__ void splitpk(float a, float b, uint32_t& hi, uint32_t& lo) {
    __nv_bfloat162 h = __floats2bfloat162_rn(a, b);
    float ra = a - __bfloat162float(h.x);
    float rb = b - __bfloat162float(h.y);
    __nv_bfloat162 l = __floats2bfloat162_rn(ra, rb);
    hi = *(uint32_t*)&h; lo = *(uint32_t*)&l;
}
#define CPA16(sa, gp) asm volatile("cp.async.cg.shared.global [%0], [%1], 16;" :: "r"(sa), "l"(gp))
#define CP_COMMIT()   asm volatile("cp.async.commit_group;")
#define CP_WAIT1()    asm volatile("cp.async.wait_group 1;" ::: "memory")

// ---------------- fused weight convert + transpose (all 8) ----------------
__global__ void __launch_bounds__(256) cvt_wt_all_kernel(
    const float* __restrict__ W0, const float* __restrict__ W1,
    const float* __restrict__ W2, const float* __restrict__ W3,
    const float* __restrict__ W4, const float* __restrict__ W5,
    const float* __restrict__ W6, const float* __restrict__ W7,
    __nv_bfloat16* __restrict__ hi, __nv_bfloat16* __restrict__ lo) {
    int w = blockIdx.y;
    const float* W = (w == 0) ? W0 : (w == 1) ? W1 : (w == 2) ? W2 : (w == 3) ? W3 :
                     (w == 4) ? W4 : (w == 5) ? W5 : (w == 6) ? W6 : W7;
    int idx = blockIdx.x * 256 + threadIdx.x;   // idx = n*512 + k
    int n = idx >> 9, k = idx & 511;
    float v = W[k * Dq + n];
    __nv_bfloat16 h = __float2bfloat16(v);
    size_t o = (size_t)w * Dq * Dq + idx;
    hi[o] = h;
    lo[o] = __float2bfloat16(v - __bfloat162float(h));
}

// ---------------- positional-embedding add (fp32 + split bf16 out) ----------------
__global__ void __launch_bounds__(256) add_pos_kernel(const float* __restrict__ x,
                                                      float* __restrict__ out,
                                                      __nv_bfloat16* __restrict__ ohi,
                                                      __nv_bfloat16* __restrict__ olo) {
    int idx = blockIdx.x * 256 + threadIdx.x;
    int d = idx & (Dq - 1);
    int s = (idx >> 9) & (Sq - 1);
    float freq  = expf((float)d * -0.0359778920794f);
    float angle = (float)s * freq;
    float pe = (d & 1) ? cosf(angle) : sinf(angle);
    float r = x[idx] + pe;
    out[idx] = r;
    __nv_bfloat16 h = __float2bfloat16(r);
    ohi[idx] = h;
    olo[idx] = __float2bfloat16(r - __bfloat162float(h));
}

// ---------------- fused LayerNorm + residual ----------------
__global__ void __launch_bounds__(256) ln_add_kernel(const float* __restrict__ x,
                                                     const float* __restrict__ gamma,
                                                     const float* __restrict__ beta,
                                                     const float* __restrict__ basep,
                                                     float scale,
                                                     float* __restrict__ out,
                                                     __nv_bfloat16* __restrict__ ohi,
                                                     __nv_bfloat16* __restrict__ olo) {
    __shared__ float red[256];
    int t = threadIdx.x;
    size_t off = (size_t)blockIdx.x * Dq;

    float v0 = x[off + t];
    float v1 = x[off + t + 256];

    red[t] = v0 + v1;
    __syncthreads();
    #pragma unroll
    for (int s2 = 128; s2 > 0; s2 >>= 1) {
        if (t < s2) red[t] += red[t + s2];
        __syncthreads();
    }
    float mu = red[0] * (1.0f / 512.0f);
    __syncthreads();

    float d0 = v0 - mu, d1 = v1 - mu;
    red[t] = d0 * d0 + d1 * d1;
    __syncthreads();
    #pragma unroll
    for (int s2 = 128; s2 > 0; s2 >>= 1) {
        if (t < s2) red[t] += red[t + s2];
        __syncthreads();
    }
    float var = red[0] * (1.0f / 512.0f);
    float rs  = rsqrtf(var + 1e-3f);

    float r0 = basep[off + t]       + scale * (d0 * rs * gamma[t]       + beta[t]);
    float r1 = basep[off + t + 256] + scale * (d1 * rs * gamma[t + 256] + beta[t + 256]);
    out[off + t]       = r0;
    out[off + t + 256] = r1;
    if (ohi) {
        __nv_bfloat16 h0 = __float2bfloat16(r0), h1 = __float2bfloat16(r1);
        ohi[off + t]       = h0;
        ohi[off + t + 256] = h1;
        olo[off + t]       = __float2bfloat16(r0 - __bfloat162float(h0));
        olo[off + t + 256] = __float2bfloat16(r1 - __bfloat162float(h1));
    }
}

// ---------------- mma.sync split-bf16 GEMM (R5 single-buffer, proven fast) ----------------
#define APAD 72
#define SA_HI 0
#define SA_LO 18432
#define SB_HI 36864
#define SB_LO 46080
#define GEMM_SMEM 55296

__global__ void __launch_bounds__(256) gemm_mma_kernel(const __nv_bfloat16* __restrict__ Ahi,
                                                       const __nv_bfloat16* __restrict__ Alo,
                                                       const __nv_bfloat16* __restrict__ Bhi,
                                                       const __nv_bfloat16* __restrict__ Blo,
                                                       const float* __restrict__ addend,
                                                       float* __restrict__ C,
                                                       __nv_bfloat16* __restrict__ Chi,
                                                       __nv_bfloat16* __restrict__ Clo) {
    extern __shared__ char smem[];
    uint32_t sb = smem_u32(smem);
    __nv_bfloat16* sAhi = (__nv_bfloat16*)(smem + SA_HI);
    __nv_bfloat16* sAlo = (__nv_bfloat16*)(smem + SA_LO);
    __nv_bfloat16* sBhi = (__nv_bfloat16*)(smem + SB_HI);
    __nv_bfloat16* sBlo = (__nv_bfloat16*)(smem + SB_LO);

    int tid = threadIdx.x;
    int wid = tid >> 5, lane = tid & 31;
    int wm = (wid & 3) * 32;
    int wn = (wid >> 2) * 32;
    int m0 = blockIdx.y * 128;
    int n0 = blockIdx.x * 64;

    float acc[2][4][4];
    #pragma unroll
    for (int i = 0; i < 2; i++)
        #pragma unroll
        for (int j = 0; j < 4; j++)
            #pragma unroll
            for (int q = 0; q < 4; q++) acc[i][j][q] = 0.0f;

    int la = lane & 15;
    int lacol = (lane >> 4) << 3;
    int lb = lane & 7;
    int lbcol = ((lane >> 3) & 1) << 3;

    for (int kc = 0; kc < 8; kc++) {
        int kofs = kc * 64;
        #pragma unroll
        for (int p = 0; p < 4; p++) {
            int e = tid + p * 256;
            int r = e >> 3, c8 = (e & 7) * 8;
            size_t go = (size_t)(m0 + r) * Dq + kofs + c8;
            *(uint4*)&sAhi[r * APAD + c8] = *(const uint4*)&Ahi[go];
            *(uint4*)&sAlo[r * APAD + c8] = *(const uint4*)&Alo[go];
        }
        #pragma unroll
        for (int p = 0; p < 2; p++) {
            int e = tid + p * 256;
            int r = e >> 3, c8 = (e & 7) * 8;
            size_t go = (size_t)(n0 + r) * Dq + kofs + c8;
            *(uint4*)&sBhi[r * APAD + c8] = *(const uint4*)&Bhi[go];
            *(uint4*)&sBlo[r * APAD + c8] = *(const uint4*)&Blo[go];
        }
        __syncthreads();

        #pragma unroll
        for (int ks = 0; ks < 4; ks++) {
            int kk = ks * 16;
            uint32_t ah[2][4], al[2][4];
            #pragma unroll
            for (int ma = 0; ma < 2; ma++) {
                int row = wm + ma * 16 + la;
                uint32_t off = (uint32_t)((row * APAD + kk + lacol) * 2);
                ldsm_x4(ah[ma], sb + SA_HI + off);
                ldsm_x4(al[ma], sb + SA_LO + off);
            }
            uint32_t bh[4][2], bl[4][2];
            #pragma unroll
            for (int na = 0; na < 4; na++) {
                int rown = wn + na * 8 + lb;
                uint32_t off = (uint32_t)((rown * APAD + kk + lbcol) * 2);
                ldsm_x2(bh[na], sb + SB_HI + off);
                ldsm_x2(bl[na], sb + SB_LO + off);
            }
            #pragma unroll
            for (int ma = 0; ma < 2; ma++)
                #pragma unroll
                for (int na = 0; na < 4; na++) {
                    mma16816(acc[ma][na], ah[ma], bh[na]);
                    mma16816(acc[ma][na], al[ma], bh[na]);
                    mma16816(acc[ma][na], ah[ma], bl[na]);
                }
        }
        __syncthreads();
    }

    int g = lane >> 2, tq = lane & 3;
    #pragma unroll
    for (int ma = 0; ma < 2; ma++) {
        int row = m0 + wm + ma * 16 + g;
        #pragma unroll
        for (int na = 0; na < 4; na++) {
            int col = n0 + wn + na * 8 + tq * 2;
            size_t o0 = (size_t)row * Dq + col;
            size_t o1 = o0 + 8 * Dq;
            float2 r0 = make_float2(acc[ma][na][0], acc[ma][na][1]);
            float2 r1 = make_float2(acc[ma][na][2], acc[ma][na][3]);
            if (addend) {
                float2 a0 = *(const float2*)&addend[o0];
                float2 a1 = *(const float2*)&addend[o1];
                r0.x += a0.x; r0.y += a0.y;
                r1.x += a1.x; r1.y += a1.y;
            }
            if (C) {
                *(float2*)&C[o0] = r0;
                *(float2*)&C[o1] = r1;
            }
            if (Chi) {
                uint32_t h, l;
                splitpk(r0.x, r0.y, h, l);
                *(uint32_t*)&Chi[o0] = h; *(uint32_t*)&Clo[o0] = l;
                splitpk(r1.x, r1.y, h, l);
                *(uint32_t*)&Chi[o1] = h; *(uint32_t*)&Clo[o1] = l;
            }
        }
    }
}

// ---------------- mma.sync flash attention, 128q tiles + cp.async (R6, kept) ----------------
#define FP 72
#define FQHI 0
#define FQLO 18432
#define FKV  36864          // start of double buffers
#define KVH  0
#define KVL  9216
#define VVH  18432
#define VVL  27648
#define KVBUF 36864
#define FLASH_SMEM (FKV + 2 * KVBUF)   // 110592

__global__ void __launch_bounds__(256) flash_mma_kernel(
    const __nv_bfloat16* __restrict__ Qh, const __nv_bfloat16* __restrict__ Ql,
    const __nv_bfloat16* __restrict__ Kh, const __nv_bfloat16* __restrict__ Kl,
    const __nv_bfloat16* __restrict__ Vh, const __nv_bfloat16* __restrict__ Vl,
    float* __restrict__ O,
    __nv_bfloat16* __restrict__ Ohi, __nv_bfloat16* __restrict__ Olo) {
    extern __shared__ char smem[];
    uint32_t sb = smem_u32(smem);

    int tid = threadIdx.x, wid = tid >> 5, lane = tid & 31;
    int wm = wid * 16;                                   // 8 warps x 16 q-rows = 128
    int g = lane >> 2, tq = lane & 3;
    int qb = blockIdx.x, h = blockIdx.y, b = blockIdx.z;
    size_t baseQ  = ((size_t)b * Sq + (size_t)qb * 128) * Dq + h * DHq;
    size_t baseKV = (size_t)b * Sq * Dq + h * DHq;

    int rQ = tid >> 1, cQ = (tid & 1) * 32;
    int rK = tid >> 2, cK = (tid & 3) * 16;

    auto kvload = [&](int kb, uint32_t bofs) {
        size_t go = baseKV + (size_t)(kb * 64 + rK) * Dq + cK;
        uint32_t so = sb + FKV + bofs + (uint32_t)((rK * FP + cK) * 2);
        #pragma unroll
        for (int q = 0; q < 2; q++) {
            CPA16(so + KVH + q * 16, &Kh[go + q * 8]);
            CPA16(so + KVL + q * 16, &Kl[go + q * 8]);
            CPA16(so + VVH + q * 16, &Vh[go + q * 8]);
            CPA16(so + VVL + q * 16, &Vl[go + q * 8]);
        }
    };

    {
        size_t go = baseQ + (size_t)rQ * Dq + cQ;
        uint32_t so = sb + (uint32_t)((rQ * FP + cQ) * 2);
        #pragma unroll
        for (int q = 0; q < 4; q++) {
            CPA16(so + FQHI + q * 16, &Qh[go + q * 8]);
            CPA16(so + FQLO + q * 16, &Ql[go + q * 8]);
        }
        kvload(0, 0);
        CP_COMMIT();
    }

    float oacc[8][4];
    #pragma unroll
    for (int j = 0; j < 8; j++)
        #pragma unroll
        for (int q = 0; q < 4; q++) oacc[j][q] = 0.0f;
    float mr0 = -1e30f, mr1 = -1e30f, lr0 = 0.0f, lr1 = 0.0f;

    uint32_t aQ = (uint32_t)(((wm + (lane & 15)) * FP + ((lane >> 4) << 3)) * 2);
    uint32_t bK = (uint32_t)(((lane & 7) * FP + (((lane >> 3) & 1) << 3)) * 2);
    uint32_t bV = (uint32_t)(((lane & 15) * FP) * 2);

    for (int kb = 0; kb < 16; kb++) {
        uint32_t cur = FKV + ((kb & 1) ? KVBUF : 0);
        if (kb < 15) kvload(kb + 1, (kb & 1) ? 0 : KVBUF);
        CP_COMMIT();
        CP_WAIT1();
        __syncthreads();

        float sacc[8][4];
        #pragma unroll
        for (int j = 0; j < 8; j++)
            #pragma unroll
            for (int q = 0; q < 4; q++) sacc[j][q] = 0.0f;

        #pragma unroll
        for (int ks = 0; ks < 4; ks++) {
            uint32_t ah[4], al[4];
            ldsm_x4(ah, sb + FQHI + aQ + ks * 32);
            ldsm_x4(al, sb + FQLO + aQ + ks * 32);
            #pragma unroll
            for (int na = 0; na < 8; na++) {
                uint32_t bh[2], bl[2];
                uint32_t off = cur + bK + (uint32_t)(na * 8 * FP * 2) + ks * 32;
                ldsm_x2(bh, sb + KVH + off);
                ldsm_x2(bl, sb + KVL + off);
                mma16816(sacc[na], ah, bh);
                mma16816(sacc[na], al, bh);
                mma16816(sacc[na], ah, bl);
            }
        }

        float rmax0 = -1e30f, rmax1 = -1e30f;
        #pragma unroll
        for (int j = 0; j < 8; j++) {
            sacc[j][0] *= 0.125f; sacc[j][1] *= 0.125f;
            sacc[j][2] *= 0.125f; sacc[j][3] *= 0.125f;
            rmax0 = fmaxf(rmax0, fmaxf(sacc[j][0], sacc[j][1]));
            rmax1 = fmaxf(rmax1, fmaxf(sacc[j][2], sacc[j][3]));
        }
        rmax0 = fmaxf(rmax0, __shfl_xor_sync(0xffffffffu, rmax0, 1));
        rmax0 = fmaxf(rmax0, __shfl_xor_sync(0xffffffffu, rmax0, 2));
        rmax1 = fmaxf(rmax1, __shfl_xor_sync(0xffffffffu, rmax1, 1));
        rmax1 = fmaxf(rmax1, __shfl_xor_sync(0xffffffffu, rmax1, 2));
        float mn0 = fmaxf(mr0, rmax0), mn1 = fmaxf(mr1, rmax1);
        float al0 = __expf(mr0 - mn0), al1 = __expf(mr1 - mn1);
        float sum0 = 0.0f, sum1 = 0.0f;
        #pragma unroll
        for (int j = 0; j < 8; j++) {
            sacc[j][0] = __expf(sacc[j][0] - mn0);
            sacc[j][1] = __expf(sacc[j][1] - mn0);
            sacc[j][2] = __expf(sacc[j][2] - mn1);
            sacc[j][3] = __expf(sacc[j][3] - mn1);
            sum0 += sacc[j][0] + sacc[j][1];
            sum1 += sacc[j][2] + sacc[j][3];
        }
        sum0 += __shfl_xor_sync(0xffffffffu, sum0, 1);
        sum0 += __shfl_xor_sync(0xffffffffu, sum0, 2);
        sum1 += __shfl_xor_sync(0xffffffffu, sum1, 1);
        sum1 += __shfl_xor_sync(0xffffffffu, sum1, 2);
        lr0 = lr0 * al0 + sum0; mr0 = mn0;
        lr1 = lr1 * al1 + sum1; mr1 = mn1;

        #pragma unroll
        for (int j = 0; j < 8; j++) {
            oacc[j][0] *= al0; oacc[j][1] *= al0;
            oacc[j][2] *= al1; oacc[j][3] *= al1;
        }

        uint32_t ph[4][4], pl[4][4];
        #pragma unroll
        for (int k2 = 0; k2 < 4; k2++) {
            splitpk(sacc[2*k2][0],   sacc[2*k2][1],   ph[k2][0], pl[k2][0]);
            splitpk(sacc[2*k2][2],   sacc[2*k2][3],   ph[k2][1], pl[k2][1]);
            splitpk(sacc[2*k2+1][0], sacc[2*k2+1][1], ph[k2][2], pl[k2][2]);
            splitpk(sacc[2*k2+1][2], sacc[2*k2+1][3], ph[k2][3], pl[k2][3]);
        }

        #pragma unroll
        for (int k2 = 0; k2 < 4; k2++) {
            #pragma unroll
            for (int na = 0; na < 8; na++) {
                uint32_t bvh[2], bvl[2];
                uint32_t off = cur + bV + (uint32_t)((k2 * 16 * FP + na * 8) * 2);
                ldsm_x2t(bvh, sb + VVH + off);
                ldsm_x2t(bvl, sb + VVL + off);
                mma16816(oacc[na], ph[k2], bvh);
                mma16816(oacc[na], pl[k2], bvh);
                mma16816(oacc[na], ph[k2], bvl);
            }
        }
        __syncthreads();
    }

    float il0 = 1.0f / lr0, il1 = 1.0f / lr1;
    int row0 = wm + g, row1 = wm + g + 8;
    #pragma unroll
    for (int na = 0; na < 8; na++) {
        int col = na * 8 + tq * 2;
        float v00 = oacc[na][0] * il0, v01 = oacc[na][1] * il0;
        float v10 = oacc[na][2] * il1, v11 = oacc[na][3] * il1;
        size_t o0 = baseQ + (size_t)row0 * Dq + col;
        size_t o1 = baseQ + (size_t)row1 * Dq + col;
        if (O) {
            *(float2*)&O[o0] = make_float2(v00, v01);
            *(float2*)&O[o1] = make_float2(v10, v11);
        }
        if (Ohi) {
            uint32_t hh, ll;
            splitpk(v00, v01, hh, ll);
            *(uint32_t*)&Ohi[o0] = hh; *(uint32_t*)&Olo[o0] = ll;
            splitpk(v10, v11, hh, ll);
            *(uint32_t*)&Ohi[o1] = hh; *(uint32_t*)&Olo[o1] = ll;
        }
    }
}

// ---------------- launcher ----------------
extern "C" void kernel_launch(void* const* d_in, const int* in_sizes, int n_in,
                              void* d_out, int out_size) {
    const float* in0   = (const float*)d_in[0];
    const float* in1   = (const float*)d_in[1];
    const float* ge = (const float*)d_in[6];
    const float* be = (const float*)d_in[7];
    const float* gd = (const float*)d_in[12];
    const float* bd = (const float*)d_in[13];
    float* out = (float*)d_out;

    float *E, *DI, *Sb, *I, *EO;
    __nv_bfloat16 *Ahi, *Alo, *Qhi, *Qlo, *Khi, *Klo, *Vhi, *Vlo, *EOhi, *EOlo, *Whi, *Wlo;
    cudaGetSymbolAddress((void**)&E,    g_E);
    cudaGetSymbolAddress((void**)&DI,   g_DI);
    cudaGetSymbolAddress((void**)&Sb,   g_S);
    cudaGetSymbolAddress((void**)&I,    g_I);
    cudaGetSymbolAddress((void**)&EO,   g_EO);
    cudaGetSymbolAddress((void**)&Ahi,  g_Ahi);
    cudaGetSymbolAddress((void**)&Alo,  g_Alo);
    cudaGetSymbolAddress((void**)&Qhi,  g_Qhi);
    cudaGetSymbolAddress((void**)&Qlo,  g_Qlo);
    cudaGetSymbolAddress((void**)&Khi,  g_Khi);
    cudaGetSymbolAddress((void**)&Klo,  g_Klo);
    cudaGetSymbolAddress((void**)&Vhi,  g_Vhi);
    cudaGetSymbolAddress((void**)&Vlo,  g_Vlo);
    cudaGetSymbolAddress((void**)&EOhi, g_EOhi);
    cudaGetSymbolAddress((void**)&EOlo, g_EOlo);
    cudaGetSymbolAddress((void**)&Whi,  g_Wthi);
    cudaGetSymbolAddress((void**)&Wlo,  g_Wtlo);

    cudaFuncSetAttribute(gemm_mma_kernel,  cudaFuncAttributeMaxDynamicSharedMemorySize, GEMM_SMEM);
    cudaFuncSetAttribute(flash_mma_kernel, cudaFuncAttributeMaxDynamicSharedMemorySize, FLASH_SMEM);

    dim3 ggrid(Dq / 64, BSr / 128);       // (8, 64)
    dim3 fgrid(Sq / 128, Hq, Bq);         // (8, 8, 8)
    const int WSZ = Dq * Dq;

    dim3 wgrid(WSZ / 256, 8);
    cvt_wt_all_kernel<<<wgrid, 256>>>(
        (const float*)d_in[2], (const float*)d_in[3], (const float*)d_in[4],
        (const float*)d_in[5], (const float*)d_in[8], (const float*)d_in[9],
        (const float*)d_in[10], (const float*)d_in[11], Whi, Wlo);

    // ---- Encoder ----
    add_pos_kernel<<<BSD / 256, 256>>>(in0, E, Ahi, Alo);
    gemm_mma_kernel<<<ggrid, 256, GEMM_SMEM>>>(Ahi, Alo, Whi + 0 * WSZ, Wlo + 0 * WSZ, nullptr, nullptr, Qhi, Qlo);
    gemm_mma_kernel<<<ggrid, 256, GEMM_SMEM>>>(Ahi, Alo, Whi + 1 * WSZ, Wlo + 1 * WSZ, nullptr, nullptr, Khi, Klo);
    gemm_mma_kernel<<<ggrid, 256, GEMM_SMEM>>>(Ahi, Alo, Whi + 2 * WSZ, Wlo + 2 * WSZ, nullptr, nullptr, Vhi, Vlo);
    flash_mma_kernel<<<fgrid, 256, FLASH_SMEM>>>(Qhi, Qlo, Khi, Klo, Vhi, Vlo, Sb, nullptr, nullptr);
    ln_add_kernel<<<BSr, 256>>>(Sb, ge, be, E, 1.0f, I, Ahi, Alo);
    gemm_mma_kernel<<<ggrid, 256, GEMM_SMEM>>>(Ahi, Alo, Whi + 3 * WSZ, Wlo + 3 * WSZ, E, EO, EOhi, EOlo);

    // ---- Decoder ----
    add_pos_kernel<<<BSD / 256, 256>>>(in1, DI, Ahi, Alo);
    gemm_mma_kernel<<<ggrid, 256, GEMM_SMEM>>>(Ahi, Alo, Whi + 4 * WSZ, Wlo + 4 * WSZ, nullptr, nullptr, Qhi, Qlo);
    gemm_mma_kernel<<<ggrid, 256, GEMM_SMEM>>>(Ahi, Alo, Whi + 5 * WSZ, Wlo + 5 * WSZ, nullptr, nullptr, Khi, Klo);
    gemm_mma_kernel<<<ggrid, 256, GEMM_SMEM>>>(Ahi, Alo, Whi + 6 * WSZ, Wlo + 6 * WSZ, nullptr, nullptr, Vhi, Vlo);
    flash_mma_kernel<<<fgrid, 256, FLASH_SMEM>>>(Qhi, Qlo, Khi, Klo, Vhi, Vlo, Sb, nullptr, nullptr);
    ln_add_kernel<<<BSr, 256>>>(Sb, gd, bd, DI, 2.0f, I, nullptr, nullptr);
    flash_mma_kernel<<<fgrid, 256, FLASH_SMEM>>>(EOhi, EOlo, EOhi, EOlo, EOhi, EOlo,
                                                 nullptr, Ahi, Alo);   // eda -> bf16 only
    gemm_mma_kernel<<<ggrid, 256, GEMM_SMEM>>>(Ahi, Alo, Whi + 7 * WSZ, Wlo + 7 * WSZ, I, out, nullptr, nullptr);
}